// round 12
// baseline (speedup 1.0000x reference)
#include <cuda_runtime.h>
#include <cuda_bf16.h>
#include <math.h>

// Problem constants
#define BB   128
#define HH   512
#define DD   64
#define SS   512
#define LBL  96
#define PRD  192
#define DECL (LBL + PRD)     // 288
#define TTF  (SS + LBL)      // 608 teacher-forced steps

#define KC   32              // K chunk
#define NTHR 256             // threads per CTA
#define NCTA 128             // CTAs (<= 148 SMs -> co-resident, barrier-safe)
#define HSTR 129             // hs row stride (odd -> conflict-free STS)
#define WSTR 18              // ws row stride (8B-aligned float2, 2-way STS)

// Persistent device state (allocation-free scratch).
// __align__(16): these are accessed with float4/float2 vector loads.
__device__ __align__(16) float g_h[2][2][BB * HH];   // [layer][pingpong][B*H]
__device__ __align__(16) float g_c[2][BB * HH];      // [layer][B*H] (CTA-private)
__device__ __align__(16) float g_pred[BB * DD];      // AR feedback
__device__ unsigned g_bar_count;
__device__ volatile unsigned g_bar_sense;

struct __align__(16) Smem {
    float hs[KC][HSTR];   // input chunk  [k][row]
    float ws[KC][WSTR];   // weight chunk [k][gatecol]
};

// ---------------------------------------------------------------------------
// Sense-reversing software grid barrier. All 128 CTAs are co-resident
// (grid <= SM count, 1 CTA/SM), all follow identical control flow.
__device__ __forceinline__ void grid_sync(unsigned* s_sense) {
    __syncthreads();
    if (threadIdx.x == 0) {
        unsigned want = *s_sense ^ 1u;
        *s_sense = want;
        __threadfence();                       // release CTA's global writes
        if (atomicAdd(&g_bar_count, 1u) == NCTA - 1u) {
            atomicExch(&g_bar_count, 0u);
            __threadfence();
            g_bar_sense = want;
        } else {
            while (g_bar_sense != want) __nanosleep(32);
        }
        __threadfence();                       // acquire
    }
    __syncthreads();
}

__device__ __forceinline__ float sigf(float v) { return 1.0f / (1.0f + expf(-v)); }

// ---------------------------------------------------------------------------
// One LSTM cell slice: this CTA computes gates for 4 hidden units (16 gate
// cols) x 128 batch rows, then updates its private c slice and writes h_next.
// 256 threads, thread tile = 4 rows x 2 gate cols.
// Cross-CTA data (x / h_prev) is read with __ldcg; h_next stored with __stcg.
__device__ __noinline__ void lstm_slice(
    Smem* sm,
    const float* __restrict__ x, int xstride, int in_dim,
    const float* __restrict__ Wih, const float* __restrict__ Whh,
    const float* __restrict__ bih, const float* __restrict__ bhh,
    const float* __restrict__ h_prev, float* __restrict__ h_next,
    float* __restrict__ c_st, int hb)
{
    const int tid = threadIdx.x;
    const int tc  = tid & 7;        // 0..7  -> gate col pair
    const int c0  = 2 * tc;         // cols c0, c0+1 (within 16)
    const int r0  = (tid >> 3) * 4; // rows r0..r0+3

    const int lk = tid & 31;        // k within chunk for loads
    const int lr = tid >> 5;        // 0..7

    float a0[4], a1[4];
#pragma unroll
    for (int i = 0; i < 4; ++i) { a0[i] = 0.0f; a1[i] = 0.0f; }

#pragma unroll 1
    for (int pass = 0; pass < 2; ++pass) {
        const float* src  = pass ? h_prev : x;
        const float* W    = pass ? Whh    : Wih;
        const int    K    = pass ? HH     : in_dim;
        const int    sstr = pass ? HH     : xstride;

#pragma unroll 1
        for (int k0 = 0; k0 < K; k0 += KC) {
            // load input chunk: 128 rows x 32 k. LDG coalesced (k contiguous),
            // STS stride 129 -> conflict-free.
            {
                const float* s = src + k0 + lk;
#pragma unroll
                for (int i = 0; i < 16; ++i) {
                    int row = lr + 8 * i;
                    sm->hs[lk][row] = __ldcg(s + (size_t)row * sstr);
                }
            }
            // load weight chunk: 16 gate cols x 32 k (coalesced LDG, L1-cached)
            {
#pragma unroll
                for (int i = 0; i < 2; ++i) {
                    int cc = lr + 8 * i;                      // gate col 0..15
                    int j  = (cc & 3) * HH + hb + (cc >> 2);  // global gate row
                    sm->ws[lk][cc] = W[(size_t)j * K + k0 + lk];
                }
            }
            __syncthreads();

#pragma unroll
            for (int k = 0; k < KC; ++k) {
                float2 wv = *(const float2*)&sm->ws[k][c0];
                float h0 = sm->hs[k][r0 + 0];
                float h1 = sm->hs[k][r0 + 1];
                float h2 = sm->hs[k][r0 + 2];
                float h3 = sm->hs[k][r0 + 3];
                a0[0] = fmaf(h0, wv.x, a0[0]);  a1[0] = fmaf(h0, wv.y, a1[0]);
                a0[1] = fmaf(h1, wv.x, a0[1]);  a1[1] = fmaf(h1, wv.y, a1[1]);
                a0[2] = fmaf(h2, wv.x, a0[2]);  a1[2] = fmaf(h2, wv.y, a1[2]);
                a0[3] = fmaf(h3, wv.x, a0[3]);  a1[3] = fmaf(h3, wv.y, a1[3]);
            }
            __syncthreads();
        }
    }

    // bias + gate exchange + cell update.
    // even tc holds (i,f), odd tc holds (g,o) of unit u = tc>>1; partner lane^1.
    const int j0 = (c0 & 3) * HH + hb + (c0 >> 2);
    const int j1 = ((c0 + 1) & 3) * HH + hb + ((c0 + 1) >> 2);
    const float b0 = bih[j0] + bhh[j0];
    const float b1 = bih[j1] + bhh[j1];
    const int  u    = tc >> 1;
    const bool even = (tc & 1) == 0;

#pragma unroll
    for (int i = 0; i < 4; ++i) {
        float ga = a0[i] + b0;                         // i-gate (even) / g (odd)
        float gb = a1[i] + b1;                         // f-gate (even) / o (odd)
        float pa = __shfl_xor_sync(0xffffffffu, ga, 1);
        float pb = __shfl_xor_sync(0xffffffffu, gb, 1);
        if (even) {
            float iv = sigf(ga);
            float fv = sigf(gb);
            float gv = tanhf(pa);
            float ov = sigf(pb);
            int gidx = (r0 + i) * HH + hb + u;
            float cv = fv * c_st[gidx] + iv * gv;      // c is CTA-private
            c_st[gidx] = cv;
            __stcg(&h_next[gidx], ov * tanhf(cv));
        }
    }
}

// ---------------------------------------------------------------------------
// Projection: CTA b computes pred[b, 0:64] = h1[b,:] @ W.T + bias.
// Warp w handles output dim d = p*8 + w; lanes split K, coalesced LDG.
__device__ __forceinline__ void proj_slice(
    const float* __restrict__ W, const float* __restrict__ bias,
    const float* __restrict__ h1, float* __restrict__ out_step)
{
    const int bI = blockIdx.x;
    const float* hrow = h1 + (size_t)bI * HH;   // 16B-aligned: g_h aligned, bI*HH*4 % 16 == 0
    const int w = threadIdx.x >> 5;
    const int l = threadIdx.x & 31;

#pragma unroll
    for (int p = 0; p < 8; ++p) {
        int d = p * 8 + w;
        const float* wr = W + (size_t)d * HH;
        float s = 0.0f;
#pragma unroll
        for (int m = 0; m < 4; ++m) {
            int k = m * 128 + 4 * l;
            float4 wv = *(const float4*)(wr + k);
            float4 hv = __ldcg((const float4*)(hrow + k));
            s = fmaf(wv.x, hv.x, s);
            s = fmaf(wv.y, hv.y, s);
            s = fmaf(wv.z, hv.z, s);
            s = fmaf(wv.w, hv.w, s);
        }
#pragma unroll
        for (int o = 16; o; o >>= 1) s += __shfl_xor_sync(0xffffffffu, s, o);
        if (l == 0) {
            float v = s + bias[d];
            out_step[(size_t)bI * (PRD * DD) + d] = v;
            __stcg(&g_pred[bI * DD + d], v);
        }
    }
}

// ---------------------------------------------------------------------------
__global__ void __launch_bounds__(NTHR, 1)
lstm_persistent(const float* __restrict__ x_enc, const float* __restrict__ x_dec,
                const float* eWih0, const float* eWhh0, const float* ebih0, const float* ebhh0,
                const float* eWih1, const float* eWhh1, const float* ebih1, const float* ebhh1,
                const float* dWih0, const float* dWhh0, const float* dbih0, const float* dbhh0,
                const float* dWih1, const float* dWhh1, const float* dbih1, const float* dbhh1,
                const float* projW, const float* projB,
                float* __restrict__ out)
{
    __shared__ Smem sm;
    __shared__ unsigned s_sense;
    const int tid = threadIdx.x;
    const int hb  = blockIdx.x * 4;        // this CTA's 4 hidden units

    if (tid == 0) s_sense = g_bar_sense;   // read before any barrier; consistent

    // zero initial h, c (only parity-0 h buffers are ever read uninitialized)
    for (int i = blockIdx.x * NTHR + tid; i < BB * HH; i += NCTA * NTHR) {
        g_h[0][0][i] = 0.0f; g_h[1][0][i] = 0.0f;
        g_c[0][i]    = 0.0f; g_c[1][i]    = 0.0f;
    }
    grid_sync(&s_sense);

    int p0 = 0, p1 = 0;

    // ---- Teacher-forced region, software-pipelined:
    // phase t: layer0(t) and layer1(t-1) both read h0(t-1) -> 1 barrier/step.
    for (int t = 0; t <= TTF; ++t) {
        if (t < TTF) {
            const float* xp; int xs;
            const float *Wi, *Wh, *bi, *bh;
            if (t < SS) { xp = x_enc + (size_t)t * DD;        xs = SS * DD;
                          Wi = eWih0; Wh = eWhh0; bi = ebih0; bh = ebhh0; }
            else        { xp = x_dec + (size_t)(t - SS) * DD; xs = DECL * DD;
                          Wi = dWih0; Wh = dWhh0; bi = dbih0; bh = dbhh0; }
            lstm_slice(&sm, xp, xs, DD, Wi, Wh, bi, bh,
                       g_h[0][p0], g_h[0][p0 ^ 1], g_c[0], hb);
        }
        if (t >= 1) {
            int tt = t - 1;
            const float *Wi, *Wh, *bi, *bh;
            if (tt < SS) { Wi = eWih1; Wh = eWhh1; bi = ebih1; bh = ebhh1; }
            else         { Wi = dWih1; Wh = dWhh1; bi = dbih1; bh = dbhh1; }
            lstm_slice(&sm, g_h[0][p0], HH, HH, Wi, Wh, bi, bh,
                       g_h[1][p1], g_h[1][p1 ^ 1], g_c[1], hb);
        }
        grid_sync(&s_sense);
        if (t < TTF) p0 ^= 1;
        if (t >= 1)  p1 ^= 1;
    }

    // pred0 from last teacher-forced h1 -> out[:, 0, :] and g_pred
    proj_slice(projW, projB, g_h[1][p1], out);
    grid_sync(&s_sense);

    // ---- Autoregressive region: strictly serial layer0 -> layer1 -> proj
    for (int s = 1; s < PRD; ++s) {
        lstm_slice(&sm, g_pred, DD, DD, dWih0, dWhh0, dbih0, dbhh0,
                   g_h[0][p0], g_h[0][p0 ^ 1], g_c[0], hb);
        grid_sync(&s_sense);
        p0 ^= 1;

        lstm_slice(&sm, g_h[0][p0], HH, HH, dWih1, dWhh1, dbih1, dbhh1,
                   g_h[1][p1], g_h[1][p1 ^ 1], g_c[1], hb);
        grid_sync(&s_sense);
        p1 ^= 1;

        proj_slice(projW, projB, g_h[1][p1], out + (size_t)s * DD);
        grid_sync(&s_sense);
    }
}

// ---------------------------------------------------------------------------
extern "C" void kernel_launch(void* const* d_in, const int* in_sizes, int n_in,
                              void* d_out, int out_size)
{
    const float* x_enc = (const float*)d_in[0];
    const float* x_dec = (const float*)d_in[2];
    const float* eWih0 = (const float*)d_in[4];
    const float* eWhh0 = (const float*)d_in[5];
    const float* ebih0 = (const float*)d_in[6];
    const float* ebhh0 = (const float*)d_in[7];
    const float* eWih1 = (const float*)d_in[8];
    const float* eWhh1 = (const float*)d_in[9];
    const float* ebih1 = (const float*)d_in[10];
    const float* ebhh1 = (const float*)d_in[11];
    const float* dWih0 = (const float*)d_in[12];
    const float* dWhh0 = (const float*)d_in[13];
    const float* dbih0 = (const float*)d_in[14];
    const float* dbhh0 = (const float*)d_in[15];
    const float* dWih1 = (const float*)d_in[16];
    const float* dWhh1 = (const float*)d_in[17];
    const float* dbih1 = (const float*)d_in[18];
    const float* dbhh1 = (const float*)d_in[19];
    const float* projW = (const float*)d_in[20];
    const float* projB = (const float*)d_in[21];
    float* out = (float*)d_out;

    lstm_persistent<<<NCTA, NTHR>>>(
        x_enc, x_dec,
        eWih0, eWhh0, ebih0, ebhh0,
        eWih1, eWhh1, ebih1, ebhh1,
        dWih0, dWhh0, dbih0, dbhh0,
        dWih1, dWhh1, dbih1, dbhh1,
        projW, projB, out);
}

// round 13
// speedup vs baseline: 1.4625x; 1.4625x over previous
#include <cuda_runtime.h>
#include <cuda_bf16.h>
#include <math.h>

// Problem constants
#define BB   128
#define HH   512
#define DD   64
#define SS   512
#define LBL  96
#define PRD  192
#define DECL (LBL + PRD)     // 288
#define TTF  (SS + LBL)      // 608 teacher-forced steps

#define NTHR 256             // threads per CTA (8 warps)
#define NCTA 128             // CTAs
#define KCE  64              // bf16 elems per K chunk
#define KW   32              // 32-bit words per chunk row
#define HST  36              // hs row stride in words (36 % 32 == 4 -> conflict-free)
#define WST  36              // ws row stride in words

// Split-weight segment offsets (elements)
#define SZ0 (4*HH*DD)        // 131072
#define SZH (4*HH*HH)        // 1048576
#define O_EW0I 0
#define O_EW0H (O_EW0I + SZ0)
#define O_EW1I (O_EW0H + SZH)
#define O_EW1H (O_EW1I + SZH)
#define O_DW0I (O_EW1H + SZH)
#define O_DW0H (O_DW0I + SZ0)
#define O_DW1I (O_DW0H + SZH)
#define O_DW1H (O_DW1I + SZH)
#define WTOT   (O_DW1H + SZH)   // 6,553,600 elems

// Persistent device state (allocation-free scratch)
__device__ __align__(16) __nv_bfloat16 g_whi[WTOT];        // weight hi parts
__device__ __align__(16) __nv_bfloat16 g_wlo[WTOT];        // weight lo parts
__device__ __align__(16) __nv_bfloat16 g_hh[2][2][BB*HH];  // h hi  [layer][pp]
__device__ __align__(16) __nv_bfloat16 g_hl[2][2][BB*HH];  // h lo  [layer][pp]
__device__ __align__(16) float         g_h1f[BB*HH];       // layer1 h fp32 (for proj)
__device__ __align__(16) float         g_c[2][BB*HH];      // cell state (CTA-private slices)
__device__ __align__(16) __nv_bfloat16 g_ph[BB*DD];        // pred hi (AR feedback)
__device__ __align__(16) __nv_bfloat16 g_pl[BB*DD];        // pred lo
__device__ unsigned g_bar_count;
__device__ volatile unsigned g_bar_sense;

struct __align__(16) Smem {
    unsigned hs_hi[BB * HST];   // A chunk hi: [row][kword]
    unsigned hs_lo[BB * HST];   // A chunk lo
    unsigned ws_hi[16 * WST];   // B chunk hi: [gatecol][kword]
    unsigned ws_lo[16 * WST];   // B chunk lo
};                              // ~41.5 KB

// ---------------------------------------------------------------------------
// Weight split prep: fp32 -> (hi, lo) bf16. One-off per launch.
__global__ void prep_weights(const float* e0i, const float* e0h,
                             const float* e1i, const float* e1h,
                             const float* d0i, const float* d0h,
                             const float* d1i, const float* d1h)
{
    const float* src; int off, n;
    switch (blockIdx.y) {
        case 0: src = e0i; off = O_EW0I; n = SZ0; break;
        case 1: src = e0h; off = O_EW0H; n = SZH; break;
        case 2: src = e1i; off = O_EW1I; n = SZH; break;
        case 3: src = e1h; off = O_EW1H; n = SZH; break;
        case 4: src = d0i; off = O_DW0I; n = SZ0; break;
        case 5: src = d0h; off = O_DW0H; n = SZH; break;
        case 6: src = d1i; off = O_DW1I; n = SZH; break;
        default: src = d1h; off = O_DW1H; n = SZH; break;
    }
    for (int i = blockIdx.x * blockDim.x + threadIdx.x; i < n;
         i += gridDim.x * blockDim.x) {
        float v = src[i];
        __nv_bfloat16 h = __float2bfloat16(v);
        float lo = v - __bfloat162float(h);
        g_whi[off + i] = h;
        g_wlo[off + i] = __float2bfloat16(lo);
    }
}

// ---------------------------------------------------------------------------
__device__ __forceinline__ void grid_sync(unsigned* s_sense) {
    __syncthreads();
    if (threadIdx.x == 0) {
        unsigned want = *s_sense ^ 1u;
        *s_sense = want;
        __threadfence();
        if (atomicAdd(&g_bar_count, 1u) == NCTA - 1u) {
            atomicExch(&g_bar_count, 0u);
            __threadfence();
            g_bar_sense = want;
        } else {
            while (g_bar_sense != want) __nanosleep(32);
        }
        __threadfence();
    }
    __syncthreads();
}

__device__ __forceinline__ float sigf(float v) { return 1.0f / (1.0f + __expf(-v)); }
__device__ __forceinline__ float tanhfast(float v) { return 2.0f / (1.0f + __expf(-2.0f * v)) - 1.0f; }

__device__ __forceinline__ void mma16816(float* d, const unsigned* a,
                                         unsigned b0, unsigned b1) {
    asm volatile(
        "mma.sync.aligned.m16n8k16.row.col.f32.bf16.bf16.f32 "
        "{%0,%1,%2,%3}, {%4,%5,%6,%7}, {%8,%9}, {%0,%1,%2,%3};"
        : "+f"(d[0]), "+f"(d[1]), "+f"(d[2]), "+f"(d[3])
        : "r"(a[0]), "r"(a[1]), "r"(a[2]), "r"(a[3]), "r"(b0), "r"(b1));
}

__device__ __forceinline__ void st_bf16_cg(__nv_bfloat16* p, __nv_bfloat16 v) {
    asm volatile("st.global.cg.u16 [%0], %1;"
                 :: "l"(p), "h"(__bfloat16_as_ushort(v)) : "memory");
}

// ---------------------------------------------------------------------------
// Staging helpers: fill SMEM chunk [128 rows x 32 words] (k-contiguous words).
// Cross-CTA sources read via __ldcg (L1 non-coherent across CTAs).
__device__ __forceinline__ void stage_bf16(unsigned* dhi, unsigned* dlo,
        const __nv_bfloat16* shi, const __nv_bfloat16* slo,
        int k0, int sstr, int tid)
{
    const unsigned* ghi = (const unsigned*)shi;
    const unsigned* glo = (const unsigned*)slo;
#pragma unroll
    for (int it = 0; it < 16; ++it) {
        int idx = tid + it * NTHR;       // 0..4095
        int row = idx >> 5;
        int p   = idx & 31;
        size_t gw = (((size_t)row * sstr + k0) >> 1) + p;
        dhi[row * HST + p] = __ldcg(ghi + gw);
        dlo[row * HST + p] = __ldcg(glo + gw);
    }
}

__device__ __forceinline__ void stage_f32(unsigned* dhi, unsigned* dlo,
        const float* x, int k0, int sstr, int tid)
{
#pragma unroll
    for (int it = 0; it < 16; ++it) {
        int idx = tid + it * NTHR;
        int row = idx >> 5;
        int p   = idx & 31;
        float2 v = *(const float2*)(x + (size_t)row * sstr + k0 + 2 * p);
        __nv_bfloat16 h0 = __float2bfloat16(v.x);
        __nv_bfloat16 h1 = __float2bfloat16(v.y);
        float l0 = v.x - __bfloat162float(h0);
        float l1 = v.y - __bfloat162float(h1);
        unsigned wh = (unsigned)__bfloat16_as_ushort(h0) |
                      ((unsigned)__bfloat16_as_ushort(h1) << 16);
        unsigned wl = (unsigned)__bfloat16_as_ushort(__float2bfloat16(l0)) |
                      ((unsigned)__bfloat16_as_ushort(__float2bfloat16(l1)) << 16);
        dhi[row * HST + p] = wh;
        dlo[row * HST + p] = wl;
    }
}

__device__ __forceinline__ void stage_w(unsigned* dhi, unsigned* dlo,
        const __nv_bfloat16* Whi, const __nv_bfloat16* Wlo,
        int K, int k0, int hb, int tid)
{
    int c  = tid >> 4;                                 // gate col 0..15
    int w0 = tid & 15;
    int j  = (c & 3) * HH + hb + (c >> 2);             // global gate row
    size_t gw = ((size_t)j * K + k0) >> 1;
    const unsigned* gh = (const unsigned*)Whi + gw;
    const unsigned* gl = (const unsigned*)Wlo + gw;
    dhi[c * WST + w0]      = gh[w0];
    dhi[c * WST + w0 + 16] = gh[w0 + 16];
    dlo[c * WST + w0]      = gl[w0];
    dlo[c * WST + w0 + 16] = gl[w0 + 16];
}

// ---------------------------------------------------------------------------
// One LSTM cell slice using split-bf16 MMA.
// CTA owns 16 gate cols (4 hidden units) x 128 batch rows.
// Warp w computes rows [16w, 16w+16) x all 16 cols via 2 n8-halves.
__device__ __noinline__ void lstm_slice(Smem* sm,
    const float* xf, const __nv_bfloat16* xh, const __nv_bfloat16* xl,
    int xstr, int xK,
    const __nv_bfloat16* Wih_hi, const __nv_bfloat16* Wih_lo,
    const __nv_bfloat16* Whh_hi, const __nv_bfloat16* Whh_lo,
    const float* __restrict__ bih, const float* __restrict__ bhh,
    const __nv_bfloat16* hp_hi, const __nv_bfloat16* hp_lo,
    __nv_bfloat16* hn_hi, __nv_bfloat16* hn_lo, float* hn_f,
    float* c_st, int hb)
{
    const int tid  = threadIdx.x;
    const int w    = tid >> 5;
    const int lane = tid & 31;
    const int tq   = lane >> 2;   // 0..7
    const int tp   = lane & 3;    // 0..3

    float d0[4] = {0.f, 0.f, 0.f, 0.f};
    float d1[4] = {0.f, 0.f, 0.f, 0.f};

    const unsigned* Ah  = sm->hs_hi + (w * 16 + tq) * HST;
    const unsigned* Ah8 = Ah + 8 * HST;
    const unsigned* Al  = sm->hs_lo + (w * 16 + tq) * HST;
    const unsigned* Al8 = Al + 8 * HST;
    const unsigned* B0h = sm->ws_hi + tq * WST;
    const unsigned* B1h = B0h + 8 * WST;
    const unsigned* B0l = sm->ws_lo + tq * WST;
    const unsigned* B1l = B0l + 8 * WST;

#pragma unroll 1
    for (int pass = 0; pass < 2; ++pass) {
        const int K = pass ? HH : xK;
        const __nv_bfloat16* Whi = pass ? Whh_hi : Wih_hi;
        const __nv_bfloat16* Wlo = pass ? Whh_lo : Wih_lo;

#pragma unroll 1
        for (int k0 = 0; k0 < K; k0 += KCE) {
            __syncthreads();   // previous chunk's MMA reads done
            if (pass == 1)      stage_bf16(sm->hs_hi, sm->hs_lo, hp_hi, hp_lo, k0, HH, tid);
            else if (xf)        stage_f32 (sm->hs_hi, sm->hs_lo, xf, k0, xstr, tid);
            else                stage_bf16(sm->hs_hi, sm->hs_lo, xh, xl, k0, xstr, tid);
            stage_w(sm->ws_hi, sm->ws_lo, Whi, Wlo, K, k0, hb, tid);
            __syncthreads();

#pragma unroll
            for (int s = 0; s < 4; ++s) {
                const int kw = s * 8 + tp;
                unsigned ahv[4] = {Ah[kw], Ah8[kw], Ah[kw + 4], Ah8[kw + 4]};
                unsigned alv[4] = {Al[kw], Al8[kw], Al[kw + 4], Al8[kw + 4]};
                unsigned bh0a = B0h[kw], bh0b = B0h[kw + 4];
                unsigned bh1a = B1h[kw], bh1b = B1h[kw + 4];
                unsigned bl0a = B0l[kw], bl0b = B0l[kw + 4];
                unsigned bl1a = B1l[kw], bl1b = B1l[kw + 4];
                mma16816(d0, ahv, bh0a, bh0b);
                mma16816(d0, ahv, bl0a, bl0b);
                mma16816(d0, alv, bh0a, bh0b);
                mma16816(d1, ahv, bh1a, bh1b);
                mma16816(d1, ahv, bl1a, bl1b);
                mma16816(d1, alv, bh1a, bh1b);
            }
        }
    }

    // Epilogue: bias + i/f <-> g/o exchange (lane t <-> t^1) + cell update.
    // Lane holds (rows tq, tq+8 of its warp tile) x cols {2tp, 2tp+1} per half.
#pragma unroll
    for (int nh = 0; nh < 2; ++nh) {
        float* d = nh ? d1 : d0;
        int cA = nh * 8 + 2 * tp;
        int cB = cA + 1;
        int jA = (cA & 3) * HH + hb + (cA >> 2);
        int jB = (cB & 3) * HH + hb + (cB >> 2);
        float bA = bih[jA] + bhh[jA];
        float bB = bih[jB] + bhh[jB];
        float v0 = d[0] + bA, v1 = d[1] + bB;
        float v2 = d[2] + bA, v3 = d[3] + bB;
        float p0 = __shfl_xor_sync(0xffffffffu, v0, 1);
        float p1 = __shfl_xor_sync(0xffffffffu, v1, 1);
        float p2 = __shfl_xor_sync(0xffffffffu, v2, 1);
        float p3 = __shfl_xor_sync(0xffffffffu, v3, 1);
        if ((tp & 1) == 0) {   // even tp holds (i,f); partner holds (g,o)
            int u  = cA >> 2;                 // unit 0..3
            int m0 = w * 16 + tq;
#pragma unroll
            for (int rr = 0; rr < 2; ++rr) {
                float iv = sigf(rr ? v2 : v0);
                float fv = sigf(rr ? v3 : v1);
                float gv = tanhfast(rr ? p2 : p0);
                float ov = sigf(rr ? p3 : p1);
                int gidx = (m0 + rr * 8) * HH + hb + u;
                float cv = fv * c_st[gidx] + iv * gv;
                c_st[gidx] = cv;
                float hv = ov * tanhfast(cv);
                __nv_bfloat16 hbf = __float2bfloat16(hv);
                float lo = hv - __bfloat162float(hbf);
                st_bf16_cg(&hn_hi[gidx], hbf);
                st_bf16_cg(&hn_lo[gidx], __float2bfloat16(lo));
                if (hn_f) __stcg(&hn_f[gidx], hv);
            }
        }
    }
}

// ---------------------------------------------------------------------------
// Projection: CTA b computes pred[b, 0:64] = h1[b,:] @ W.T + bias (fp32),
// writes output slice + split-bf16 AR feedback.
__device__ __forceinline__ void proj_slice(
    const float* __restrict__ W, const float* __restrict__ bias,
    const float* __restrict__ h1, float* __restrict__ out_step)
{
    const int bI = blockIdx.x;
    const float* hrow = h1 + (size_t)bI * HH;
    const int w = threadIdx.x >> 5;
    const int l = threadIdx.x & 31;

#pragma unroll
    for (int p = 0; p < 8; ++p) {
        int dcol = p * 8 + w;
        const float* wr = W + (size_t)dcol * HH;
        float s = 0.0f;
#pragma unroll
        for (int m = 0; m < 4; ++m) {
            int k = m * 128 + 4 * l;
            float4 wv = *(const float4*)(wr + k);
            float4 hv = __ldcg((const float4*)(hrow + k));
            s = fmaf(wv.x, hv.x, s);
            s = fmaf(wv.y, hv.y, s);
            s = fmaf(wv.z, hv.z, s);
            s = fmaf(wv.w, hv.w, s);
        }
#pragma unroll
        for (int o = 16; o; o >>= 1) s += __shfl_xor_sync(0xffffffffu, s, o);
        if (l == 0) {
            float v = s + bias[dcol];
            out_step[(size_t)bI * (PRD * DD) + dcol] = v;
            __nv_bfloat16 hbf = __float2bfloat16(v);
            float lo = v - __bfloat162float(hbf);
            st_bf16_cg(&g_ph[bI * DD + dcol], hbf);
            st_bf16_cg(&g_pl[bI * DD + dcol], __float2bfloat16(lo));
        }
    }
}

// ---------------------------------------------------------------------------
__global__ void __launch_bounds__(NTHR, 1)
lstm_persistent(const float* __restrict__ x_enc, const float* __restrict__ x_dec,
                const float* ebih0, const float* ebhh0,
                const float* ebih1, const float* ebhh1,
                const float* dbih0, const float* dbhh0,
                const float* dbih1, const float* dbhh1,
                const float* projW, const float* projB,
                float* __restrict__ out)
{
    __shared__ Smem sm;
    __shared__ unsigned s_sense;
    const int tid = threadIdx.x;
    const int hb  = blockIdx.x * 4;

    if (tid == 0) s_sense = g_bar_sense;

    // zero initial state (parity-0 h buffers + c)
    const unsigned short z = 0;
    for (int i = blockIdx.x * NTHR + tid; i < BB * HH; i += NCTA * NTHR) {
        g_hh[0][0][i] = __ushort_as_bfloat16(z);
        g_hh[1][0][i] = __ushort_as_bfloat16(z);
        g_hl[0][0][i] = __ushort_as_bfloat16(z);
        g_hl[1][0][i] = __ushort_as_bfloat16(z);
        g_c[0][i] = 0.0f; g_c[1][i] = 0.0f;
    }
    grid_sync(&s_sense);

    int p0 = 0, p1 = 0;

    // ---- Teacher-forced region (pipelined: layer0(t) || layer1(t-1)) ----
    for (int t = 0; t <= TTF; ++t) {
        if (t < TTF) {
            bool enc = t < SS;
            const float* xp = enc ? x_enc + (size_t)t * DD
                                  : x_dec + (size_t)(t - SS) * DD;
            int xs = enc ? SS * DD : DECL * DD;
            lstm_slice(&sm, xp, nullptr, nullptr, xs, DD,
                g_whi + (enc ? O_EW0I : O_DW0I), g_wlo + (enc ? O_EW0I : O_DW0I),
                g_whi + (enc ? O_EW0H : O_DW0H), g_wlo + (enc ? O_EW0H : O_DW0H),
                enc ? ebih0 : dbih0, enc ? ebhh0 : dbhh0,
                g_hh[0][p0], g_hl[0][p0],
                g_hh[0][p0 ^ 1], g_hl[0][p0 ^ 1], nullptr,
                g_c[0], hb);
        }
        if (t >= 1) {
            bool enc = (t - 1) < SS;
            lstm_slice(&sm, nullptr, g_hh[0][p0], g_hl[0][p0], HH, HH,
                g_whi + (enc ? O_EW1I : O_DW1I), g_wlo + (enc ? O_EW1I : O_DW1I),
                g_whi + (enc ? O_EW1H : O_DW1H), g_wlo + (enc ? O_EW1H : O_DW1H),
                enc ? ebih1 : dbih1, enc ? ebhh1 : dbhh1,
                g_hh[1][p1], g_hl[1][p1],
                g_hh[1][p1 ^ 1], g_hl[1][p1 ^ 1], g_h1f,
                g_c[1], hb);
        }
        grid_sync(&s_sense);
        if (t < TTF) p0 ^= 1;
        if (t >= 1)  p1 ^= 1;
    }

    // pred0 -> out[:, 0, :] and AR feedback
    proj_slice(projW, projB, g_h1f, out);
    grid_sync(&s_sense);

    // ---- Autoregressive region ----
    for (int s = 1; s < PRD; ++s) {
        lstm_slice(&sm, nullptr, g_ph, g_pl, DD, DD,
            g_whi + O_DW0I, g_wlo + O_DW0I, g_whi + O_DW0H, g_wlo + O_DW0H,
            dbih0, dbhh0,
            g_hh[0][p0], g_hl[0][p0],
            g_hh[0][p0 ^ 1], g_hl[0][p0 ^ 1], nullptr,
            g_c[0], hb);
        grid_sync(&s_sense);
        p0 ^= 1;

        lstm_slice(&sm, nullptr, g_hh[0][p0], g_hl[0][p0], HH, HH,
            g_whi + O_DW1I, g_wlo + O_DW1I, g_whi + O_DW1H, g_wlo + O_DW1H,
            dbih1, dbhh1,
            g_hh[1][p1], g_hl[1][p1],
            g_hh[1][p1 ^ 1], g_hl[1][p1 ^ 1], g_h1f,
            g_c[1], hb);
        grid_sync(&s_sense);
        p1 ^= 1;

        proj_slice(projW, projB, g_h1f, out + (size_t)s * DD);
        grid_sync(&s_sense);
    }
}

// ---------------------------------------------------------------------------
extern "C" void kernel_launch(void* const* d_in, const int* in_sizes, int n_in,
                              void* d_out, int out_size)
{
    const float* x_enc = (const float*)d_in[0];
    const float* x_dec = (const float*)d_in[2];
    const float* eWih0 = (const float*)d_in[4];
    const float* eWhh0 = (const float*)d_in[5];
    const float* ebih0 = (const float*)d_in[6];
    const float* ebhh0 = (const float*)d_in[7];
    const float* eWih1 = (const float*)d_in[8];
    const float* eWhh1 = (const float*)d_in[9];
    const float* ebih1 = (const float*)d_in[10];
    const float* ebhh1 = (const float*)d_in[11];
    const float* dWih0 = (const float*)d_in[12];
    const float* dWhh0 = (const float*)d_in[13];
    const float* dbih0 = (const float*)d_in[14];
    const float* dbhh0 = (const float*)d_in[15];
    const float* dWih1 = (const float*)d_in[16];
    const float* dWhh1 = (const float*)d_in[17];
    const float* dbih1 = (const float*)d_in[18];
    const float* dbhh1 = (const float*)d_in[19];
    const float* projW = (const float*)d_in[20];
    const float* projB = (const float*)d_in[21];
    float* out = (float*)d_out;

    // 1) split weights into bf16 hi/lo (one-off per launch; 2-node graph)
    prep_weights<<<dim3(256, 8), 256>>>(eWih0, eWhh0, eWih1, eWhh1,
                                        dWih0, dWhh0, dWih1, dWhh1);

    // 2) persistent seq2seq LSTM
    lstm_persistent<<<NCTA, NTHR>>>(
        x_enc, x_dec,
        ebih0, ebhh0, ebih1, ebhh1,
        dbih0, dbhh0, dbih1, dbhh1,
        projW, projB, out);
}

// round 14
// speedup vs baseline: 2.0507x; 1.4022x over previous
#include <cuda_runtime.h>
#include <cuda_bf16.h>
#include <math.h>

// Problem constants
#define BB   128
#define HH   512
#define DD   64
#define SS   512
#define LBL  96
#define PRD  192
#define DECL (LBL + PRD)     // 288
#define TTF  (SS + LBL)      // 608 teacher-forced steps

#define NTHR 256             // threads per CTA (8 warps)
#define NCTA 128             // CTAs
#define AST  36              // A-chunk row stride in words (36 % 32 == 4)
#define NC0  9               // layer0 chunks: (64 + 512) / 64
#define NC1  16              // layer1 chunks: (512 + 512) / 64
#define W0S  292             // layer0 weight row stride words (288 + 4)
#define W1S  516             // layer1 weight row stride words (512 + 4)

// Split-weight segment offsets (elements)
#define SZ0 (4*HH*DD)
#define SZH (4*HH*HH)
#define O_EW0I 0
#define O_EW0H (O_EW0I + SZ0)
#define O_EW1I (O_EW0H + SZH)
#define O_EW1H (O_EW1I + SZH)
#define O_DW0I (O_EW1H + SZH)
#define O_DW0H (O_DW0I + SZ0)
#define O_DW1I (O_DW0H + SZH)
#define O_DW1H (O_DW1I + SZH)
#define WTOT   (O_DW1H + SZH)

// Persistent device state (allocation-free scratch)
__device__ __align__(16) __nv_bfloat16 g_whi[WTOT];
__device__ __align__(16) __nv_bfloat16 g_wlo[WTOT];
__device__ __align__(16) __nv_bfloat16 g_xeh[BB*SS*DD];    // x_enc hi
__device__ __align__(16) __nv_bfloat16 g_xel[BB*SS*DD];    // x_enc lo
__device__ __align__(16) __nv_bfloat16 g_xdh[BB*DECL*DD];  // x_dec hi
__device__ __align__(16) __nv_bfloat16 g_xdl[BB*DECL*DD];  // x_dec lo
__device__ __align__(16) __nv_bfloat16 g_hh[2][2][BB*HH];  // h hi [layer][pp]
__device__ __align__(16) __nv_bfloat16 g_hl[2][2][BB*HH];  // h lo
__device__ __align__(16) float         g_h1f[BB*HH];       // layer1 h fp32 (proj)
__device__ __align__(16) float         g_c[2][BB*HH];      // cell state (CTA-private)
__device__ __align__(16) __nv_bfloat16 g_ph[BB*DD];        // pred hi (AR feedback)
__device__ __align__(16) __nv_bfloat16 g_pl[BB*DD];        // pred lo
__device__ unsigned g_bar_count;
__device__ volatile unsigned g_bar_sense;

struct Smem {
    unsigned w0hi[16*W0S], w0lo[16*W0S];        // layer0 weights (ih|hh fused K)
    unsigned w1hi[16*W1S], w1lo[16*W1S];        // layer1 weights
    unsigned ahi[2][BB*AST], alo[2][BB*AST];    // double-buffered A chunks
};                                              // 177,152 bytes

// ---------------------------------------------------------------------------
// Prep: split fp32 -> (hi, lo) bf16 for weights and inputs. One-off.
__global__ void prep_split(const float* e0i, const float* e0h,
                           const float* e1i, const float* e1h,
                           const float* d0i, const float* d0h,
                           const float* d1i, const float* d1h,
                           const float* xe, const float* xd)
{
    const float* src; __nv_bfloat16 *dh, *dl; int n;
    switch (blockIdx.y) {
        case 0: src = e0i; dh = g_whi + O_EW0I; dl = g_wlo + O_EW0I; n = SZ0; break;
        case 1: src = e0h; dh = g_whi + O_EW0H; dl = g_wlo + O_EW0H; n = SZH; break;
        case 2: src = e1i; dh = g_whi + O_EW1I; dl = g_wlo + O_EW1I; n = SZH; break;
        case 3: src = e1h; dh = g_whi + O_EW1H; dl = g_wlo + O_EW1H; n = SZH; break;
        case 4: src = d0i; dh = g_whi + O_DW0I; dl = g_wlo + O_DW0I; n = SZ0; break;
        case 5: src = d0h; dh = g_whi + O_DW0H; dl = g_wlo + O_DW0H; n = SZH; break;
        case 6: src = d1i; dh = g_whi + O_DW1I; dl = g_wlo + O_DW1I; n = SZH; break;
        case 7: src = d1h; dh = g_whi + O_DW1H; dl = g_wlo + O_DW1H; n = SZH; break;
        case 8: src = xe;  dh = g_xeh; dl = g_xel; n = BB*SS*DD;   break;
        default: src = xd; dh = g_xdh; dl = g_xdl; n = BB*DECL*DD; break;
    }
    for (int i = blockIdx.x * blockDim.x + threadIdx.x; i < n;
         i += gridDim.x * blockDim.x) {
        float v = src[i];
        __nv_bfloat16 h = __float2bfloat16(v);
        dh[i] = h;
        dl[i] = __float2bfloat16(v - __bfloat162float(h));
    }
}

// ---------------------------------------------------------------------------
__device__ __forceinline__ void grid_sync(unsigned* s_sense) {
    __syncthreads();
    if (threadIdx.x == 0) {
        unsigned want = *s_sense ^ 1u;
        *s_sense = want;
        __threadfence();
        if (atomicAdd(&g_bar_count, 1u) == NCTA - 1u) {
            atomicExch(&g_bar_count, 0u);
            __threadfence();
            g_bar_sense = want;
        } else {
            while (g_bar_sense != want) __nanosleep(32);
        }
        __threadfence();
    }
    __syncthreads();
}

__device__ __forceinline__ float sigf(float v) { return 1.0f / (1.0f + __expf(-v)); }
__device__ __forceinline__ float tanhfast(float v) { return 2.0f / (1.0f + __expf(-2.0f * v)) - 1.0f; }

__device__ __forceinline__ void mma16816(float* d, const unsigned* a,
                                         unsigned b0, unsigned b1) {
    asm volatile(
        "mma.sync.aligned.m16n8k16.row.col.f32.bf16.bf16.f32 "
        "{%0,%1,%2,%3}, {%4,%5,%6,%7}, {%8,%9}, {%0,%1,%2,%3};"
        : "+f"(d[0]), "+f"(d[1]), "+f"(d[2]), "+f"(d[3])
        : "r"(a[0]), "r"(a[1]), "r"(a[2]), "r"(a[3]), "r"(b0), "r"(b1));
}

__device__ __forceinline__ void st_bf16_cg(__nv_bfloat16* p, __nv_bfloat16 v) {
    asm volatile("st.global.cg.u16 [%0], %1;"
                 :: "l"(p), "h"(__bfloat16_as_ushort(v)) : "memory");
}

__device__ __forceinline__ void cp_async16(void* s, const void* g) {
    unsigned sa = (unsigned)__cvta_generic_to_shared(s);
    asm volatile("cp.async.cg.shared.global [%0], [%1], 16;"
                 :: "r"(sa), "l"(g) : "memory");
}
#define CP_COMMIT() asm volatile("cp.async.commit_group;" ::: "memory")
#define CP_WAIT1()  asm volatile("cp.async.wait_group 1;" ::: "memory")
#define CP_WAIT0()  asm volatile("cp.async.wait_group 0;" ::: "memory")

// ---------------------------------------------------------------------------
// Load this CTA's 16-gate-row weight slice (ih|hh fused along K) into SMEM.
// Sources are word pointers into the pre-split hi/lo weight pools.
__device__ void load_weights(unsigned* whi, unsigned* wlo, int WS, int xK,
                             const unsigned* ihh, const unsigned* ihl,
                             const unsigned* hhh, const unsigned* hhl,
                             int hb, int tid)
{
    const int xw = xK >> 1;                 // ih words per row
    const int twords = (xK + HH) >> 1;      // total words per row
    for (int idx = tid; idx < 16 * twords; idx += NTHR) {
        int c = idx / twords;
        int w = idx - c * twords;
        int j = (c & 3) * HH + hb + (c >> 2);
        unsigned vh, vl;
        if (w < xw) { vh = ihh[j * xw + w];          vl = ihl[j * xw + w]; }
        else        { vh = hhh[j * 256 + (w - xw)];  vl = hhl[j * 256 + (w - xw)]; }
        whi[c * WS + w] = vh;
        wlo[c * WS + w] = vl;
    }
    __syncthreads();
}

// ---------------------------------------------------------------------------
// One LSTM cell slice: split-bf16 MMA, persistent SMEM weights,
// double-buffered cp.async A staging. CTA owns 16 gate cols x 128 rows.
__device__ __noinline__ void lstm_slice(Smem* sm,
    const __nv_bfloat16* a0h, const __nv_bfloat16* a0l, int a0str, int n0,
    const __nv_bfloat16* hph, const __nv_bfloat16* hpl,
    const unsigned* whi, const unsigned* wlo, int WS, int NC,
    const float* __restrict__ bih, const float* __restrict__ bhh,
    __nv_bfloat16* hnh, __nv_bfloat16* hnl, float* hnf,
    float* c_st, int hb)
{
    const int tid  = threadIdx.x;
    const int w    = tid >> 5;
    const int lane = tid & 31;
    const int tq   = lane >> 2;   // 0..7
    const int tp   = lane & 3;    // 0..3

    auto stage = [&](int c, int buf) {
        const __nv_bfloat16 *sh, *sl; int k0, str;
        if (c < n0) { sh = a0h; sl = a0l; k0 = c * 64;        str = a0str; }
        else        { sh = hph; sl = hpl; k0 = (c - n0) * 64; str = HH;   }
        unsigned* dh = sm->ahi[buf];
        unsigned* dl = sm->alo[buf];
#pragma unroll
        for (int i = 0; i < 4; ++i) {
            int o   = tid + i * NTHR;
            int row = o >> 3, seg = o & 7;
            size_t ge = (size_t)row * str + k0 + seg * 8;
            int sw = row * AST + seg * 4;
            cp_async16(dh + sw, sh + ge);
            cp_async16(dl + sw, sl + ge);
        }
    };

    float d0[4] = {0.f, 0.f, 0.f, 0.f};
    float d1[4] = {0.f, 0.f, 0.f, 0.f};

    const unsigned* B0h = whi + tq * WS;
    const unsigned* B1h = B0h + 8 * WS;
    const unsigned* B0l = wlo + tq * WS;
    const unsigned* B1l = B0l + 8 * WS;

    __syncthreads();               // previous slice fully done with A buffers
    stage(0, 0);
    CP_COMMIT();

#pragma unroll 1
    for (int c = 0; c < NC; ++c) {
        __syncthreads();           // prior chunk's MMA reads of buf[(c+1)&1] done
        if (c + 1 < NC) { stage(c + 1, (c + 1) & 1); CP_COMMIT(); CP_WAIT1(); }
        else            { CP_WAIT0(); }
        __syncthreads();           // buf[c&1] visible to all threads

        const unsigned* Ah  = sm->ahi[c & 1] + (w * 16 + tq) * AST;
        const unsigned* Ah8 = Ah + 8 * AST;
        const unsigned* Al  = sm->alo[c & 1] + (w * 16 + tq) * AST;
        const unsigned* Al8 = Al + 8 * AST;
        const int cb = c * 32;

#pragma unroll
        for (int s = 0; s < 4; ++s) {
            const int kw = s * 8 + tp;
            unsigned ahv[4] = {Ah[kw], Ah8[kw], Ah[kw + 4], Ah8[kw + 4]};
            unsigned alv[4] = {Al[kw], Al8[kw], Al[kw + 4], Al8[kw + 4]};
            unsigned bh0a = B0h[cb + kw], bh0b = B0h[cb + kw + 4];
            unsigned bh1a = B1h[cb + kw], bh1b = B1h[cb + kw + 4];
            unsigned bl0a = B0l[cb + kw], bl0b = B0l[cb + kw + 4];
            unsigned bl1a = B1l[cb + kw], bl1b = B1l[cb + kw + 4];
            mma16816(d0, ahv, bh0a, bh0b);
            mma16816(d0, ahv, bl0a, bl0b);
            mma16816(d0, alv, bh0a, bh0b);
            mma16816(d1, ahv, bh1a, bh1b);
            mma16816(d1, ahv, bl1a, bl1b);
            mma16816(d1, alv, bh1a, bh1b);
        }
    }

    // Epilogue: bias + i/f <-> g/o exchange (lane t <-> t^1) + cell update.
#pragma unroll
    for (int nh = 0; nh < 2; ++nh) {
        float* d = nh ? d1 : d0;
        int cA = nh * 8 + 2 * tp;
        int cB = cA + 1;
        int jA = (cA & 3) * HH + hb + (cA >> 2);
        int jB = (cB & 3) * HH + hb + (cB >> 2);
        float bA = bih[jA] + bhh[jA];
        float bB = bih[jB] + bhh[jB];
        float v0 = d[0] + bA, v1 = d[1] + bB;
        float v2 = d[2] + bA, v3 = d[3] + bB;
        float p0 = __shfl_xor_sync(0xffffffffu, v0, 1);
        float p1 = __shfl_xor_sync(0xffffffffu, v1, 1);
        float p2 = __shfl_xor_sync(0xffffffffu, v2, 1);
        float p3 = __shfl_xor_sync(0xffffffffu, v3, 1);
        if ((tp & 1) == 0) {       // even tp holds (i,f); partner holds (g,o)
            int u  = cA >> 2;
            int m0 = w * 16 + tq;
#pragma unroll
            for (int rr = 0; rr < 2; ++rr) {
                float iv = sigf(rr ? v2 : v0);
                float fv = sigf(rr ? v3 : v1);
                float gv = tanhfast(rr ? p2 : p0);
                float ov = sigf(rr ? p3 : p1);
                int gidx = (m0 + rr * 8) * HH + hb + u;
                float cv = fv * c_st[gidx] + iv * gv;
                c_st[gidx] = cv;
                float hv = ov * tanhfast(cv);
                __nv_bfloat16 hbf = __float2bfloat16(hv);
                st_bf16_cg(&hnh[gidx], hbf);
                st_bf16_cg(&hnl[gidx], __float2bfloat16(hv - __bfloat162float(hbf)));
                if (hnf) __stcg(&hnf[gidx], hv);
            }
        }
    }
}

// ---------------------------------------------------------------------------
// Projection: CTA b computes pred[b, 0:64] = h1[b,:] @ W.T + bias (fp32).
// W/bias are launch-constant -> L1-cached; h1 cross-CTA -> __ldcg.
__device__ __forceinline__ void proj_slice(
    const float* __restrict__ W, const float* __restrict__ bias,
    const float* __restrict__ h1, float* __restrict__ out_step)
{
    const int bI = blockIdx.x;
    const float* hrow = h1 + (size_t)bI * HH;
    const int w = threadIdx.x >> 5;
    const int l = threadIdx.x & 31;

#pragma unroll
    for (int p = 0; p < 8; ++p) {
        int dcol = p * 8 + w;
        const float* wr = W + (size_t)dcol * HH;
        float s = 0.0f;
#pragma unroll
        for (int m = 0; m < 4; ++m) {
            int k = m * 128 + 4 * l;
            float4 wv = *(const float4*)(wr + k);
            float4 hv = __ldcg((const float4*)(hrow + k));
            s = fmaf(wv.x, hv.x, s);
            s = fmaf(wv.y, hv.y, s);
            s = fmaf(wv.z, hv.z, s);
            s = fmaf(wv.w, hv.w, s);
        }
#pragma unroll
        for (int o = 16; o; o >>= 1) s += __shfl_xor_sync(0xffffffffu, s, o);
        if (l == 0) {
            float v = s + bias[dcol];
            out_step[(size_t)bI * (PRD * DD) + dcol] = v;
            __nv_bfloat16 hbf = __float2bfloat16(v);
            st_bf16_cg(&g_ph[bI * DD + dcol], hbf);
            st_bf16_cg(&g_pl[bI * DD + dcol], __float2bfloat16(v - __bfloat162float(hbf)));
        }
    }
}

// ---------------------------------------------------------------------------
__global__ void __launch_bounds__(NTHR, 1)
lstm_persistent(const float* ebih0, const float* ebhh0,
                const float* ebih1, const float* ebhh1,
                const float* dbih0, const float* dbhh0,
                const float* dbih1, const float* dbhh1,
                const float* projW, const float* projB,
                float* __restrict__ out)
{
    extern __shared__ char smem_raw[];
    Smem* sm = (Smem*)smem_raw;
    __shared__ unsigned s_sense;
    const int tid = threadIdx.x;
    const int hb  = blockIdx.x * 4;

    if (tid == 0) s_sense = g_bar_sense;

    const unsigned short z = 0;
    for (int i = blockIdx.x * NTHR + tid; i < BB * HH; i += NCTA * NTHR) {
        g_hh[0][0][i] = __ushort_as_bfloat16(z);
        g_hh[1][0][i] = __ushort_as_bfloat16(z);
        g_hl[0][0][i] = __ushort_as_bfloat16(z);
        g_hl[1][0][i] = __ushort_as_bfloat16(z);
        g_c[0][i] = 0.0f; g_c[1][i] = 0.0f;
    }
    grid_sync(&s_sense);

    int p0 = 0, p1 = 0;

    // ---- Teacher-forced region (pipelined: layer0(t) || layer1(t-1)) ----
    for (int t = 0; t <= TTF; ++t) {
        // region weight (re)loads: enc at t=0; dec l0 at t=SS, dec l1 at t=SS+1
        if (t == 0) {
            load_weights(sm->w0hi, sm->w0lo, W0S, DD,
                (const unsigned*)(g_whi + O_EW0I), (const unsigned*)(g_wlo + O_EW0I),
                (const unsigned*)(g_whi + O_EW0H), (const unsigned*)(g_wlo + O_EW0H), hb, tid);
            load_weights(sm->w1hi, sm->w1lo, W1S, HH,
                (const unsigned*)(g_whi + O_EW1I), (const unsigned*)(g_wlo + O_EW1I),
                (const unsigned*)(g_whi + O_EW1H), (const unsigned*)(g_wlo + O_EW1H), hb, tid);
        }
        if (t == SS)
            load_weights(sm->w0hi, sm->w0lo, W0S, DD,
                (const unsigned*)(g_whi + O_DW0I), (const unsigned*)(g_wlo + O_DW0I),
                (const unsigned*)(g_whi + O_DW0H), (const unsigned*)(g_wlo + O_DW0H), hb, tid);
        if (t == SS + 1)
            load_weights(sm->w1hi, sm->w1lo, W1S, HH,
                (const unsigned*)(g_whi + O_DW1I), (const unsigned*)(g_wlo + O_DW1I),
                (const unsigned*)(g_whi + O_DW1H), (const unsigned*)(g_wlo + O_DW1H), hb, tid);

        if (t < TTF) {
            bool enc = t < SS;
            const __nv_bfloat16* xh = enc ? g_xeh + (size_t)t * DD
                                          : g_xdh + (size_t)(t - SS) * DD;
            const __nv_bfloat16* xl = enc ? g_xel + (size_t)t * DD
                                          : g_xdl + (size_t)(t - SS) * DD;
            int xs = enc ? SS * DD : DECL * DD;
            lstm_slice(sm, xh, xl, xs, 1,
                       g_hh[0][p0], g_hl[0][p0],
                       sm->w0hi, sm->w0lo, W0S, NC0,
                       enc ? ebih0 : dbih0, enc ? ebhh0 : dbhh0,
                       g_hh[0][p0 ^ 1], g_hl[0][p0 ^ 1], nullptr,
                       g_c[0], hb);
        }
        if (t >= 1) {
            bool enc = (t - 1) < SS;
            lstm_slice(sm, g_hh[0][p0], g_hl[0][p0], HH, 8,
                       g_hh[1][p1], g_hl[1][p1],
                       sm->w1hi, sm->w1lo, W1S, NC1,
                       enc ? ebih1 : dbih1, enc ? ebhh1 : dbhh1,
                       g_hh[1][p1 ^ 1], g_hl[1][p1 ^ 1], g_h1f,
                       g_c[1], hb);
        }
        grid_sync(&s_sense);
        if (t < TTF) p0 ^= 1;
        if (t >= 1)  p1 ^= 1;
    }

    // pred0 -> out[:, 0, :] and AR feedback
    proj_slice(projW, projB, g_h1f, out);
    grid_sync(&s_sense);

    // ---- Autoregressive region ----
    for (int s = 1; s < PRD; ++s) {
        lstm_slice(sm, g_ph, g_pl, DD, 1,
                   g_hh[0][p0], g_hl[0][p0],
                   sm->w0hi, sm->w0lo, W0S, NC0,
                   dbih0, dbhh0,
                   g_hh[0][p0 ^ 1], g_hl[0][p0 ^ 1], nullptr,
                   g_c[0], hb);
        grid_sync(&s_sense);
        p0 ^= 1;

        lstm_slice(sm, g_hh[0][p0], g_hl[0][p0], HH, 8,
                   g_hh[1][p1], g_hl[1][p1],
                   sm->w1hi, sm->w1lo, W1S, NC1,
                   dbih1, dbhh1,
                   g_hh[1][p1 ^ 1], g_hl[1][p1 ^ 1], g_h1f,
                   g_c[1], hb);
        grid_sync(&s_sense);
        p1 ^= 1;

        proj_slice(projW, projB, g_h1f, out + (size_t)s * DD);
        grid_sync(&s_sense);
    }
}

// ---------------------------------------------------------------------------
extern "C" void kernel_launch(void* const* d_in, const int* in_sizes, int n_in,
                              void* d_out, int out_size)
{
    const float* x_enc = (const float*)d_in[0];
    const float* x_dec = (const float*)d_in[2];
    const float* eWih0 = (const float*)d_in[4];
    const float* eWhh0 = (const float*)d_in[5];
    const float* ebih0 = (const float*)d_in[6];
    const float* ebhh0 = (const float*)d_in[7];
    const float* eWih1 = (const float*)d_in[8];
    const float* eWhh1 = (const float*)d_in[9];
    const float* ebih1 = (const float*)d_in[10];
    const float* ebhh1 = (const float*)d_in[11];
    const float* dWih0 = (const float*)d_in[12];
    const float* dWhh0 = (const float*)d_in[13];
    const float* dbih0 = (const float*)d_in[14];
    const float* dbhh0 = (const float*)d_in[15];
    const float* dWih1 = (const float*)d_in[16];
    const float* dWhh1 = (const float*)d_in[17];
    const float* dbih1 = (const float*)d_in[18];
    const float* dbhh1 = (const float*)d_in[19];
    const float* projW = (const float*)d_in[20];
    const float* projB = (const float*)d_in[21];
    float* out = (float*)d_out;

    static int smem_set = 0;
    if (!smem_set) {
        cudaFuncSetAttribute(lstm_persistent,
                             cudaFuncAttributeMaxDynamicSharedMemorySize,
                             (int)sizeof(Smem));
        smem_set = 1;
    }

    // 1) split weights + inputs into bf16 hi/lo (one-off; 2-node graph)
    prep_split<<<dim3(512, 10), 256>>>(eWih0, eWhh0, eWih1, eWhh1,
                                       dWih0, dWhh0, dWih1, dWhh1,
                                       x_enc, x_dec);

    // 2) persistent seq2seq LSTM
    lstm_persistent<<<NCTA, NTHR, sizeof(Smem)>>>(
        ebih0, ebhh0, ebih1, ebhh1,
        dbih0, dbhh0, dbih1, dbhh1,
        projW, projB, out);
}